// round 3
// baseline (speedup 1.0000x reference)
#include <cuda_runtime.h>
#include <math.h>

// Problem constants: N=16384, H=32, G=8, D=128, FF=2, R=4, GROUPS=4, NBAND=32
#define NTOK 16384
#define QK_TPB 8
#define W_TPB 8
#define NQK (NTOK / QK_TPB)   // 2048 qk blocks
#define NW  (NTOK / W_TPB)    // 2048 w blocks

// Output layout in d_out (floats): index_q [N][4][128], index_k [N][128], weights [N][4]
#define OUT_Q_OFF ((size_t)0)
#define OUT_K_OFF ((size_t)NTOK * 512)
#define OUT_W_OFF ((size_t)NTOK * 512 + (size_t)NTOK * 128)

// Folded smem layout (conflict-free for both STS.64 and scalar LDS):
//   QF[group][hf][bm(16)][feat(16)][fbit(2)]  row stride 34 floats per bm
//   region size per (group,hf) = 16*34 = 544 floats
// band = fbit*16 + bm ; feat = ffhi*8 + gh
// smem: QF[2][4352] + KF[2][1088] = 10880 floats (43520 B); w path needs 8448.
#define SMEM_FLOATS 10880

__global__ __launch_bounds__(256) void fused_kernel(
    const float* __restrict__ q,
    const float* __restrict__ k,
    const float* __restrict__ v,
    const float* __restrict__ proj,   // [32][16][2]
    const float* __restrict__ vt,     // [32][128][4]
    float* __restrict__ out)
{
    extern __shared__ float smem[];
    const int tid = threadIdx.x;

    if (blockIdx.x < NQK) {
        // ================= QK path =================
        float* QF[2] = { smem, smem + 4352 };
        float* KF[2] = { smem + 8704, smem + 8704 + 1088 };

        const int band  = tid & 31;
        const int half  = (tid >> 5) & 1;
        const int group = tid >> 6;
        const int c_bm  = band & 15;      // compute-side bm
        const int c_s   = band >> 4;      // compute-side fbit

        // proj row for this thread's band -> registers
        float pr0[16], pr1[16];
        {
            const float2* proj2 = (const float2*)proj;
            #pragma unroll
            for (int f = 0; f < 16; f++) {
                float2 p = __ldg(&proj2[band * 16 + f]);
                pr0[f] = p.x; pr1[f] = p.y;
            }
        }

        // staging-side decomposition of this thread's float4 slot
        // e4 = tid + 256*jj ; h = e4>>5 ; d4 = e4&31 ; hf = d4>>4 ; bm = d4&15
        const int s_bm = tid & 15;
        const int s_hf = (tid >> 4) & 1;
        const int s_h0 = tid >> 5;        // + 8*jj gives head (q) / is gh (k)

        const int n0 = blockIdx.x * QK_TPB;
        const float4* q4 = (const float4*)q;
        const float4* k4 = (const float4*)k;

        // prefetch token 0
        float4 pq[4]; float4 pk;
        {
            const size_t qb = (size_t)n0 * 1024;
            #pragma unroll
            for (int jj = 0; jj < 4; jj++) pq[jj] = q4[qb + tid + 256 * jj];
            pk = k4[(size_t)n0 * 256 + tid];
        }

        #pragma unroll
        for (int tok = 0; tok < QK_TPB; tok++) {
            const int n = n0 + tok;
            float* QFb = QF[tok & 1];
            float* KFb = KF[tok & 1];

            // scatter q into folded layout (vectorized, conflict-free)
            #pragma unroll
            for (int jj = 0; jj < 4; jj++) {
                const int h  = s_h0 + 8 * jj;
                const int gh = h >> 2;
                const int gr = h & 3;
                float2* base = (float2*)(QFb + ((gr * 2 + s_hf) * 544 + s_bm * 34));
                base[gh]     = make_float2(pq[jj].x, pq[jj].y);   // feat gh,   fbit 0/1
                base[8 + gh] = make_float2(pq[jj].z, pq[jj].w);   // feat 8+gh, fbit 0/1
            }
            // scatter k
            {
                float2* base = (float2*)(KFb + (s_hf * 544 + s_bm * 34));
                base[s_h0]     = make_float2(pk.x, pk.y);
                base[8 + s_h0] = make_float2(pk.z, pk.w);
            }

            // prefetch next token before the barrier (latency overlap)
            if (tok < QK_TPB - 1) {
                const size_t qb = (size_t)(n + 1) * 1024;
                #pragma unroll
                for (int jj = 0; jj < 4; jj++) pq[jj] = q4[qb + tid + 256 * jj];
                pk = k4[(size_t)(n + 1) * 256 + tid];
            }

            __syncthreads();

            // index_q: one (group, half, band) pair per thread
            {
                const float* frow = QFb + ((group * 2 + half) * 544 + c_bm * 34 + c_s);
                float a0 = 0.f, a1 = 0.f;
                #pragma unroll
                for (int f = 0; f < 16; f++) {
                    const float x = frow[2 * f];
                    a0 = fmaf(x, pr0[f], a0);
                    a1 = fmaf(x, pr1[f], a1);
                }
                float2* o = (float2*)(out + OUT_Q_OFF + (size_t)n * 512 +
                                      group * 128 + half * 64 + band * 2);
                *o = make_float2(a0, a1);
            }
            // index_k: threads 0..63 (half = tid>>5 here, band = tid&31)
            if (tid < 64) {
                const float* frow = KFb + (half * 544 + c_bm * 34 + c_s);
                float a0 = 0.f, a1 = 0.f;
                #pragma unroll
                for (int f = 0; f < 16; f++) {
                    const float x = frow[2 * f];
                    a0 = fmaf(x, pr0[f], a0);
                    a1 = fmaf(x, pr1[f], a1);
                }
                float2* o = (float2*)(out + OUT_K_OFF + (size_t)n * 128 +
                                      half * 64 + band * 2);
                *o = make_float2(a0, a1);
            }
            // single barrier per token: buffer written at iter i+2 is
            // protected by the barrier at iter i+1 (reads at iter i drained).
        }
    } else {
        // ================= W path =================
        float* VS  = smem;            // [W_TPB][1024]
        float* RED = smem + 8192;     // [tok][g][t]

        const int dseg = tid & 7;
        const int t    = (tid >> 3) & 3;
        const int g    = tid >> 5;
        const int h    = g * 4 + t;

        // vt slice in registers
        float4 wt[16];
        {
            const float4* vt4 = (const float4*)vt;
            #pragma unroll
            for (int i = 0; i < 16; i++)
                wt[i] = __ldg(&vt4[h * 128 + dseg + 8 * i]);
        }

        const int n0 = (blockIdx.x - NQK) * W_TPB;

        // stage W_TPB v rows (coalesced)
        {
            const float4* v4 = (const float4*)v + (size_t)n0 * 256;
            float4* vs4 = (float4*)VS;
            #pragma unroll
            for (int j = 0; j < W_TPB; j++)
                vs4[tid + 256 * j] = v4[tid + 256 * j];
        }
        __syncthreads();

        #pragma unroll
        for (int tok = 0; tok < W_TPB; tok++) {
            float4 a = make_float4(0.f, 0.f, 0.f, 0.f);
            float4 b = make_float4(0.f, 0.f, 0.f, 0.f);
            const float* vrow = VS + tok * 1024 + g * 128 + dseg;
            #pragma unroll
            for (int i = 0; i < 16; i += 2) {
                const float f0 = vrow[8 * i];
                const float f1 = vrow[8 * (i + 1)];
                a.x = fmaf(f0, wt[i].x, a.x);     b.x = fmaf(f1, wt[i+1].x, b.x);
                a.y = fmaf(f0, wt[i].y, a.y);     b.y = fmaf(f1, wt[i+1].y, b.y);
                a.z = fmaf(f0, wt[i].z, a.z);     b.z = fmaf(f1, wt[i+1].z, b.z);
                a.w = fmaf(f0, wt[i].w, a.w);     b.w = fmaf(f1, wt[i+1].w, b.w);
            }
            a.x += b.x; a.y += b.y; a.z += b.z; a.w += b.w;
            #pragma unroll
            for (int m = 1; m <= 4; m <<= 1) {
                a.x += __shfl_xor_sync(0xffffffffu, a.x, m);
                a.y += __shfl_xor_sync(0xffffffffu, a.y, m);
                a.z += __shfl_xor_sync(0xffffffffu, a.z, m);
                a.w += __shfl_xor_sync(0xffffffffu, a.w, m);
            }
            if (dseg == 0)
                RED[(tok * 8 + g) * 4 + t] =
                    a.x * a.x + a.y * a.y + a.z * a.z + a.w * a.w;
        }
        __syncthreads();

        if (tid < W_TPB * 4) {
            const int tok = tid >> 2;
            const int tt  = tid & 3;
            float s = 0.f;
            #pragma unroll
            for (int gg = 0; gg < 8; gg++) s += RED[(tok * 8 + gg) * 4 + tt];
            out[OUT_W_OFF + (size_t)(n0 + tok) * 4 + tt] = sqrtf(s);
        }
    }
}

extern "C" void kernel_launch(void* const* d_in, const int* in_sizes, int n_in,
                              void* d_out, int out_size)
{
    const float* q    = (const float*)d_in[0];   // [16384][32][128]
    const float* k    = (const float*)d_in[1];   // [16384][8][128]
    const float* v    = (const float*)d_in[2];   // [16384][8][128]
    const float* proj = (const float*)d_in[3];   // [32][16][2]
    const float* vt   = (const float*)d_in[4];   // [32][128][4]
    float* out = (float*)d_out;

    fused_kernel<<<NQK + NW, 256, SMEM_FLOATS * sizeof(float)>>>(
        q, k, v, proj, vt, out);
}

// round 4
// speedup vs baseline: 1.1218x; 1.1218x over previous
#include <cuda_runtime.h>
#include <math.h>

// Problem constants: N=16384, H=32, G=8, D=128, FF=2, R=4, GROUPS=4, NBAND=32
#define NTOK 16384
#define QK_TPB 8
#define W_TPB 8
#define NQK (NTOK / QK_TPB)   // 2048 qk blocks
#define NW  (NTOK / W_TPB)    // 2048 w blocks

// Output layout in d_out (floats): index_q [N][4][128], index_k [N][128], weights [N][4]
#define OUT_Q_OFF ((size_t)0)
#define OUT_K_OFF ((size_t)NTOK * 512)
#define OUT_W_OFF ((size_t)NTOK * 512 + (size_t)NTOK * 128)

// Folded smem layout (conflict-free for both STS.64 and scalar LDS):
//   QF[group][hf][bm(16)][feat(16)][fbit(2)]  row stride 34 floats per bm
//   region size per (group,hf) = 16*34 = 544 floats
// band = fbit*16 + bm ; feat = ffhi*8 + gh
// smem: QF[2][4352] + KF[2][1088] = 10880 floats (43520 B); w path needs 8448.
#define SMEM_FLOATS 10880

__global__ __launch_bounds__(256, 3) void fused_kernel(
    const float* __restrict__ q,
    const float* __restrict__ k,
    const float* __restrict__ v,
    const float* __restrict__ proj,   // [32][16][2]
    const float* __restrict__ vt,     // [32][128][4]
    float* __restrict__ out)
{
    extern __shared__ float smem[];
    const int tid = threadIdx.x;

    if (blockIdx.x < NQK) {
        // ================= QK path =================
        float* QF[2] = { smem, smem + 4352 };
        float* KF[2] = { smem + 8704, smem + 8704 + 1088 };

        const int band  = tid & 31;
        const int half  = (tid >> 5) & 1;
        const int group = tid >> 6;
        const int c_off = (band & 15) * 34 + (band >> 4);  // compute-side row offset

        // proj row for this thread's band -> registers
        float pr0[16], pr1[16];
        {
            const float2* proj2 = (const float2*)proj;
            #pragma unroll
            for (int f = 0; f < 16; f++) {
                float2 p = __ldg(&proj2[band * 16 + f]);
                pr0[f] = p.x; pr1[f] = p.y;
            }
        }

        // staging-side decomposition of this thread's float4 slot
        const int s_off = (tid & 15) * 34 + ((tid >> 4) & 1) * 544;  // bm*34 + hf*544
        const int s_h0  = tid >> 5;        // + 8*jj gives head (q) / is gh (k)

        const int n0 = blockIdx.x * QK_TPB;
        const float4* q4 = (const float4*)q;
        const float4* k4 = (const float4*)k;

        // prefetch token 0
        float4 pq[4]; float4 pk;
        {
            const size_t qb = (size_t)n0 * 1024;
            #pragma unroll
            for (int jj = 0; jj < 4; jj++) pq[jj] = q4[qb + tid + 256 * jj];
            pk = k4[(size_t)n0 * 256 + tid];
        }

        #pragma unroll
        for (int tok = 0; tok < QK_TPB; tok++) {
            const int n = n0 + tok;
            float* QFb = QF[tok & 1];
            float* KFb = KF[tok & 1];

            // scatter q into folded layout (STS.64, conflict-free)
            #pragma unroll
            for (int jj = 0; jj < 4; jj++) {
                const int h  = s_h0 + 8 * jj;
                const int gh = h >> 2;
                const int gr = h & 3;
                float2* base = (float2*)(QFb + (gr * 1088 + s_off));
                base[gh]     = make_float2(pq[jj].x, pq[jj].y);
                base[8 + gh] = make_float2(pq[jj].z, pq[jj].w);
            }
            // scatter k
            {
                float2* base = (float2*)(KFb + s_off);
                base[s_h0]     = make_float2(pk.x, pk.y);
                base[8 + s_h0] = make_float2(pk.z, pk.w);
            }

            // prefetch next token before the barrier (latency overlap)
            if (tok < QK_TPB - 1) {
                const size_t qb = (size_t)(n + 1) * 1024;
                #pragma unroll
                for (int jj = 0; jj < 4; jj++) pq[jj] = q4[qb + tid + 256 * jj];
                pk = k4[(size_t)(n + 1) * 256 + tid];
            }

            __syncthreads();

            // index_q: one (group, half, band) pair per thread
            {
                const float* frow = QFb + ((group * 2 + half) * 544 + c_off);
                float a0 = 0.f, a1 = 0.f;
                #pragma unroll
                for (int f = 0; f < 16; f++) {
                    const float x = frow[2 * f];
                    a0 = fmaf(x, pr0[f], a0);
                    a1 = fmaf(x, pr1[f], a1);
                }
                float2* o = (float2*)(out + OUT_Q_OFF + (size_t)n * 512 +
                                      group * 128 + half * 64 + band * 2);
                *o = make_float2(a0, a1);
            }
            // index_k: threads 0..63 (half = tid>>5 here, band = tid&31)
            if (tid < 64) {
                const float* frow = KFb + (half * 544 + c_off);
                float a0 = 0.f, a1 = 0.f;
                #pragma unroll
                for (int f = 0; f < 16; f++) {
                    const float x = frow[2 * f];
                    a0 = fmaf(x, pr0[f], a0);
                    a1 = fmaf(x, pr1[f], a1);
                }
                float2* o = (float2*)(out + OUT_K_OFF + (size_t)n * 128 +
                                      half * 64 + band * 2);
                *o = make_float2(a0, a1);
            }
            // single barrier per token: buffer written at iter i+2 is
            // protected by the barrier at iter i+1 (reads at iter i drained).
        }
    } else {
        // ================= W path =================
        float* VS  = smem;            // [W_TPB][1024]
        float* RED = smem + 8192;     // [tok][g][t]

        const int dseg = tid & 7;
        const int t    = (tid >> 3) & 3;
        const int g    = tid >> 5;
        const int h    = g * 4 + t;

        // vt slice in registers
        float4 wt[16];
        {
            const float4* vt4 = (const float4*)vt;
            #pragma unroll
            for (int i = 0; i < 16; i++)
                wt[i] = __ldg(&vt4[h * 128 + dseg + 8 * i]);
        }

        const int n0 = (blockIdx.x - NQK) * W_TPB;

        // stage W_TPB v rows (coalesced)
        {
            const float4* v4 = (const float4*)v + (size_t)n0 * 256;
            float4* vs4 = (float4*)VS;
            #pragma unroll
            for (int j = 0; j < W_TPB; j++)
                vs4[tid + 256 * j] = v4[tid + 256 * j];
        }
        __syncthreads();

        #pragma unroll
        for (int tok = 0; tok < W_TPB; tok++) {
            float4 a = make_float4(0.f, 0.f, 0.f, 0.f);
            float4 b = make_float4(0.f, 0.f, 0.f, 0.f);
            const float* vrow = VS + tok * 1024 + g * 128 + dseg;
            #pragma unroll
            for (int i = 0; i < 16; i += 2) {
                const float f0 = vrow[8 * i];
                const float f1 = vrow[8 * (i + 1)];
                a.x = fmaf(f0, wt[i].x, a.x);     b.x = fmaf(f1, wt[i+1].x, b.x);
                a.y = fmaf(f0, wt[i].y, a.y);     b.y = fmaf(f1, wt[i+1].y, b.y);
                a.z = fmaf(f0, wt[i].z, a.z);     b.z = fmaf(f1, wt[i+1].z, b.z);
                a.w = fmaf(f0, wt[i].w, a.w);     b.w = fmaf(f1, wt[i+1].w, b.w);
            }
            a.x += b.x; a.y += b.y; a.z += b.z; a.w += b.w;
            #pragma unroll
            for (int m = 1; m <= 4; m <<= 1) {
                a.x += __shfl_xor_sync(0xffffffffu, a.x, m);
                a.y += __shfl_xor_sync(0xffffffffu, a.y, m);
                a.z += __shfl_xor_sync(0xffffffffu, a.z, m);
                a.w += __shfl_xor_sync(0xffffffffu, a.w, m);
            }
            if (dseg == 0)
                RED[(tok * 8 + g) * 4 + t] =
                    a.x * a.x + a.y * a.y + a.z * a.z + a.w * a.w;
        }
        __syncthreads();

        if (tid < W_TPB * 4) {
            const int tok = tid >> 2;
            const int tt  = tid & 3;
            float s = 0.f;
            #pragma unroll
            for (int gg = 0; gg < 8; gg++) s += RED[(tok * 8 + gg) * 4 + tt];
            out[OUT_W_OFF + (size_t)(n0 + tok) * 4 + tt] = sqrtf(s);
        }
    }
}

extern "C" void kernel_launch(void* const* d_in, const int* in_sizes, int n_in,
                              void* d_out, int out_size)
{
    const float* q    = (const float*)d_in[0];   // [16384][32][128]
    const float* k    = (const float*)d_in[1];   // [16384][8][128]
    const float* v    = (const float*)d_in[2];   // [16384][8][128]
    const float* proj = (const float*)d_in[3];   // [32][16][2]
    const float* vt   = (const float*)d_in[4];   // [32][128][4]
    float* out = (float*)d_out;

    fused_kernel<<<NQK + NW, 256, SMEM_FLOATS * sizeof(float)>>>(
        q, k, v, proj, vt, out);
}

// round 5
// speedup vs baseline: 1.3078x; 1.1658x over previous
#include <cuda_runtime.h>
#include <math.h>

// Problem constants: N=16384, H=32, G=8, D=128, FF=2, R=4, GROUPS=4, NBAND=32
#define NTOK 16384
#define QK_TPB 8
#define W_TPB 8
#define NQK (NTOK / QK_TPB)   // 2048 qk blocks
#define NW  (NTOK / W_TPB)    // 2048 w blocks

// Output layout in d_out (floats): index_q [N][4][128], index_k [N][128], weights [N][4]
#define OUT_Q_OFF ((size_t)0)
#define OUT_K_OFF ((size_t)NTOK * 512)
#define OUT_W_OFF ((size_t)NTOK * 512 + (size_t)NTOK * 128)

// smem used only by the W path: VS[8][1024] + RED[8][8][4] = 8448 floats
#define SMEM_FLOATS 8448

// QK path (register-only fold):
//   lane = band (bm = lane&15, fbit = lane>>4).
//   float4 at (h = gh*4+gr, d = hf*64 + 4*bm) components:
//     x -> (band=bm,    feat=gh)     y -> (band=16+bm, feat=gh)
//     z -> (band=bm,    feat=8+gh)   w -> (band=16+bm, feat=8+gh)
//   Lane loads gh = fbit*4+j (j=0..3); partner lane (xor 16) has the other 4 gh.
//   One shfl_xor(16) exchange completes fold[band][0..15] per lane.

__global__ __launch_bounds__(256, 3) void fused_kernel(
    const float* __restrict__ q,
    const float* __restrict__ k,
    const float* __restrict__ v,
    const float* __restrict__ proj,   // [32][16][2]
    const float* __restrict__ vt,     // [32][128][4]
    float* __restrict__ out)
{
    extern __shared__ float smem[];
    const int tid = threadIdx.x;

    if (blockIdx.x < NQK) {
        // ================= QK path (no smem, no barriers) =================
        const int lane = tid & 31;
        const int w    = tid >> 5;        // warp 0..7
        const int bm   = lane & 15;
        const int fb   = lane >> 4;       // fbit; band == lane
        const int gr   = w & 3;           // q group for this warp
        const int hf   = w >> 2;          // q half for this warp
        const int n0   = blockIdx.x * QK_TPB;

        // ---- proj row for this lane's band, permuted into own/partner order ----
        // po_lo[j] = proj[band][fb*4+j],      po_hi[j] = proj[band][8+fb*4+j]
        // pp_lo[j] = proj[band][(fb^1)*4+j],  pp_hi[j] = proj[band][8+(fb^1)*4+j]
        float2 po_lo[4], po_hi[4], pp_lo[4], pp_hi[4];
        {
            const float4* p4 = (const float4*)(proj + lane * 32);  // this band's row
            float4 pr[8];
            #pragma unroll
            for (int m = 0; m < 8; m++) pr[m] = __ldg(&p4[m]);
            // pr[m] covers proj[band][2m..2m+1][0..1] : (f=2m:(x,y)) (f=2m+1:(z,w))
            #pragma unroll
            for (int j = 0; j < 4; j++) {
                // feat indices: own_lo = fb*4+j, own_hi = 8+fb*4+j,
                //               par_lo = (fb^1)*4+j, par_hi = 8+(fb^1)*4+j
                float2 a0j = (j & 1) ? make_float2(pr[(0 + j) >> 1].z, pr[(0 + j) >> 1].w)
                                     : make_float2(pr[(0 + j) >> 1].x, pr[(0 + j) >> 1].y);
                float2 a4j = (j & 1) ? make_float2(pr[(4 + j) >> 1].z, pr[(4 + j) >> 1].w)
                                     : make_float2(pr[(4 + j) >> 1].x, pr[(4 + j) >> 1].y);
                float2 a8j = (j & 1) ? make_float2(pr[(8 + j) >> 1].z, pr[(8 + j) >> 1].w)
                                     : make_float2(pr[(8 + j) >> 1].x, pr[(8 + j) >> 1].y);
                float2 acj = (j & 1) ? make_float2(pr[(12 + j) >> 1].z, pr[(12 + j) >> 1].w)
                                     : make_float2(pr[(12 + j) >> 1].x, pr[(12 + j) >> 1].y);
                po_lo[j] = fb ? a4j : a0j;
                pp_lo[j] = fb ? a0j : a4j;
                po_hi[j] = fb ? acj : a8j;
                pp_hi[j] = fb ? a8j : acj;
            }
        }

        // ---- K job: warp w handles token n0+w, both halves ----
        {
            const int n = n0 + w;
            const float* kb = k + (size_t)n * 1024 + 4 * bm + fb * 512; // + gh_j*128
            #pragma unroll
            for (int hh = 0; hh < 2; hh++) {
                float4 L[4];
                #pragma unroll
                for (int j = 0; j < 4; j++)
                    L[j] = __ldg((const float4*)(kb + j * 128 + hh * 64));
                float a0 = 0.f, a1 = 0.f;
                #pragma unroll
                for (int j = 0; j < 4; j++) {
                    const float oa = fb ? L[j].y : L[j].x;
                    const float ob = fb ? L[j].w : L[j].z;
                    const float sa = fb ? L[j].x : L[j].y;
                    const float sb = fb ? L[j].z : L[j].w;
                    const float ra = __shfl_xor_sync(0xffffffffu, sa, 16);
                    const float rb = __shfl_xor_sync(0xffffffffu, sb, 16);
                    a0 = fmaf(oa, po_lo[j].x, a0); a1 = fmaf(oa, po_lo[j].y, a1);
                    a0 = fmaf(ob, po_hi[j].x, a0); a1 = fmaf(ob, po_hi[j].y, a1);
                    a0 = fmaf(ra, pp_lo[j].x, a0); a1 = fmaf(ra, pp_lo[j].y, a1);
                    a0 = fmaf(rb, pp_hi[j].x, a0); a1 = fmaf(rb, pp_hi[j].y, a1);
                }
                float2* o = (float2*)(out + OUT_K_OFF + (size_t)n * 128 +
                                      hh * 64 + lane * 2);
                *o = make_float2(a0, a1);
            }
        }

        // ---- Q: loop over 8 tokens, software-pipelined ----
        // element addr for token t, load j: q + (n0+t)*4096 + (fb*4+j)*512 + gr*128 + hf*64 + 4*bm
        const float* qb = q + (size_t)n0 * 4096 + (size_t)fb * 2048 +
                          gr * 128 + hf * 64 + 4 * bm;
        float4 La[4], Lb[4];
        #pragma unroll
        for (int j = 0; j < 4; j++)
            La[j] = __ldg((const float4*)(qb + j * 512));

        #pragma unroll
        for (int t = 0; t < QK_TPB; t++) {
            float4* Lc = (t & 1) ? Lb : La;
            float4* Ln = (t & 1) ? La : Lb;
            if (t + 1 < QK_TPB) {
                const float* qn = qb + (size_t)(t + 1) * 4096;
                #pragma unroll
                for (int j = 0; j < 4; j++)
                    Ln[j] = __ldg((const float4*)(qn + j * 512));
            }
            float a0 = 0.f, a1 = 0.f;
            #pragma unroll
            for (int j = 0; j < 4; j++) {
                const float oa = fb ? Lc[j].y : Lc[j].x;
                const float ob = fb ? Lc[j].w : Lc[j].z;
                const float sa = fb ? Lc[j].x : Lc[j].y;
                const float sb = fb ? Lc[j].z : Lc[j].w;
                const float ra = __shfl_xor_sync(0xffffffffu, sa, 16);
                const float rb = __shfl_xor_sync(0xffffffffu, sb, 16);
                a0 = fmaf(oa, po_lo[j].x, a0); a1 = fmaf(oa, po_lo[j].y, a1);
                a0 = fmaf(ob, po_hi[j].x, a0); a1 = fmaf(ob, po_hi[j].y, a1);
                a0 = fmaf(ra, pp_lo[j].x, a0); a1 = fmaf(ra, pp_lo[j].y, a1);
                a0 = fmaf(rb, pp_hi[j].x, a0); a1 = fmaf(rb, pp_hi[j].y, a1);
            }
            float2* o = (float2*)(out + OUT_Q_OFF + (size_t)(n0 + t) * 512 +
                                  gr * 128 + hf * 64 + lane * 2);
            *o = make_float2(a0, a1);
        }
    } else {
        // ================= W path =================
        float* VS  = smem;            // [W_TPB][1024]
        float* RED = smem + 8192;     // [tok][g][t]

        const int dseg = tid & 7;
        const int t    = (tid >> 3) & 3;
        const int g    = tid >> 5;
        const int h    = g * 4 + t;

        // vt slice in registers
        float4 wt[16];
        {
            const float4* vt4 = (const float4*)vt;
            #pragma unroll
            for (int i = 0; i < 16; i++)
                wt[i] = __ldg(&vt4[h * 128 + dseg + 8 * i]);
        }

        const int n0 = (blockIdx.x - NQK) * W_TPB;

        // stage W_TPB v rows (coalesced)
        {
            const float4* v4 = (const float4*)v + (size_t)n0 * 256;
            float4* vs4 = (float4*)VS;
            #pragma unroll
            for (int j = 0; j < W_TPB; j++)
                vs4[tid + 256 * j] = v4[tid + 256 * j];
        }
        __syncthreads();

        #pragma unroll
        for (int tok = 0; tok < W_TPB; tok++) {
            float4 a = make_float4(0.f, 0.f, 0.f, 0.f);
            float4 b = make_float4(0.f, 0.f, 0.f, 0.f);
            const float* vrow = VS + tok * 1024 + g * 128 + dseg;
            #pragma unroll
            for (int i = 0; i < 16; i += 2) {
                const float f0 = vrow[8 * i];
                const float f1 = vrow[8 * (i + 1)];
                a.x = fmaf(f0, wt[i].x, a.x);     b.x = fmaf(f1, wt[i+1].x, b.x);
                a.y = fmaf(f0, wt[i].y, a.y);     b.y = fmaf(f1, wt[i+1].y, b.y);
                a.z = fmaf(f0, wt[i].z, a.z);     b.z = fmaf(f1, wt[i+1].z, b.z);
                a.w = fmaf(f0, wt[i].w, a.w);     b.w = fmaf(f1, wt[i+1].w, b.w);
            }
            a.x += b.x; a.y += b.y; a.z += b.z; a.w += b.w;
            #pragma unroll
            for (int m = 1; m <= 4; m <<= 1) {
                a.x += __shfl_xor_sync(0xffffffffu, a.x, m);
                a.y += __shfl_xor_sync(0xffffffffu, a.y, m);
                a.z += __shfl_xor_sync(0xffffffffu, a.z, m);
                a.w += __shfl_xor_sync(0xffffffffu, a.w, m);
            }
            if (dseg == 0)
                RED[(tok * 8 + g) * 4 + t] =
                    a.x * a.x + a.y * a.y + a.z * a.z + a.w * a.w;
        }
        __syncthreads();

        if (tid < W_TPB * 4) {
            const int tok = tid >> 2;
            const int tt  = tid & 3;
            float s = 0.f;
            #pragma unroll
            for (int gg = 0; gg < 8; gg++) s += RED[(tok * 8 + gg) * 4 + tt];
            out[OUT_W_OFF + (size_t)(n0 + tok) * 4 + tt] = sqrtf(s);
        }
    }
}

extern "C" void kernel_launch(void* const* d_in, const int* in_sizes, int n_in,
                              void* d_out, int out_size)
{
    const float* q    = (const float*)d_in[0];   // [16384][32][128]
    const float* k    = (const float*)d_in[1];   // [16384][8][128]
    const float* v    = (const float*)d_in[2];   // [16384][8][128]
    const float* proj = (const float*)d_in[3];   // [32][16][2]
    const float* vt   = (const float*)d_in[4];   // [32][128][4]
    float* out = (float*)d_out;

    fused_kernel<<<NQK + NW, 256, SMEM_FLOATS * sizeof(float)>>>(
        q, k, v, proj, vt, out);
}